// round 1
// baseline (speedup 1.0000x reference)
#include <cuda_runtime.h>
#include <math_constants.h>

#define N_NODES 1024
#define N_EDGES 32768
#define FLATD   4096   // 4*N

// -------- scratch (no allocation allowed; device globals) --------
__device__ float g_agg[FLATD];       // aggregated EdgeConv output, layout [n*4 + c]
__device__ float g_logits[N_EDGES];  // policy logits

// -------- 1) init: zero agg, seed logits with bias --------
__global__ void init_kernel(const float* __restrict__ bp) {
    int j = blockIdx.x * blockDim.x + threadIdx.x;
    if (j < N_EDGES) g_logits[j] = bp[j];
    if (j < FLATD)   g_agg[j] = 0.0f;
}

// -------- 2) EdgeConv collapsed through the one-hot --------
// h = b1 + [ti>=0]*(w1[ti] - w1[N+ti]) + [tj>=0]*w1[N+tj]; relu; @w2+b2; softmax4; scatter-add
__global__ void edge_kernel(const int* __restrict__ tgt,
                            const int* __restrict__ eidx,
                            const float* __restrict__ w1,
                            const float* __restrict__ b1,
                            const float* __restrict__ w2,
                            const float* __restrict__ b2) {
    int e = blockIdx.x * blockDim.x + threadIdx.x;
    if (e >= N_EDGES) return;
    int s = eidx[e];            // edge_index[0][e]  (source)
    int d = eidx[N_EDGES + e];  // edge_index[1][e]  (dest / aggregation node)
    int ti = tgt[d];
    int tj = tgt[s];

    float h[10];
#pragma unroll
    for (int k = 0; k < 10; k++) h[k] = b1[k];
    if (ti >= 0) {
#pragma unroll
        for (int k = 0; k < 10; k++)
            h[k] += w1[ti * 10 + k] - w1[(N_NODES + ti) * 10 + k];
    }
    if (tj >= 0) {
#pragma unroll
        for (int k = 0; k < 10; k++)
            h[k] += w1[(N_NODES + tj) * 10 + k];
    }
#pragma unroll
    for (int k = 0; k < 10; k++) h[k] = fmaxf(h[k], 0.0f);

    float m[4];
#pragma unroll
    for (int c = 0; c < 4; c++) {
        float acc = b2[c];
#pragma unroll
        for (int k = 0; k < 10; k++) acc += h[k] * w2[k * 4 + c];
        m[c] = acc;
    }
    float mx = fmaxf(fmaxf(m[0], m[1]), fmaxf(m[2], m[3]));
    float sum = 0.0f;
#pragma unroll
    for (int c = 0; c < 4; c++) { m[c] = expf(m[c] - mx); sum += m[c]; }
    float inv = 1.0f / sum;
#pragma unroll
    for (int c = 0; c < 4; c++)
        atomicAdd(&g_agg[d * 4 + c], m[c] * inv);
}

// -------- 3) policy GEMV: logits += flat @ wp  (512 MB stream, HBM-bound) --------
#define ROWS_PER_BLK 256   // FLATD / 16 row-slices
#define COLS_PER_BLK 1024  // 256 threads * 4 cols (float4)

__global__ __launch_bounds__(256) void gemv_kernel(const float* __restrict__ wp) {
    __shared__ float sx[ROWS_PER_BLK];
    int t    = threadIdx.x;
    int col  = blockIdx.x * COLS_PER_BLK + t * 4;
    int row0 = blockIdx.y * ROWS_PER_BLK;

    sx[t] = g_agg[row0 + t];   // blockDim == ROWS_PER_BLK == 256
    __syncthreads();

    float4 acc = make_float4(0.f, 0.f, 0.f, 0.f);
    const float4* wptr = reinterpret_cast<const float4*>(
        wp + (size_t)row0 * N_EDGES + col);
    const size_t stride4 = N_EDGES / 4;

#pragma unroll 4
    for (int i = 0; i < ROWS_PER_BLK; i++) {
        float  xv = sx[i];
        float4 w  = __ldcs(wptr + (size_t)i * stride4);  // streaming: no reuse
        acc.x += xv * w.x;
        acc.y += xv * w.y;
        acc.z += xv * w.z;
        acc.w += xv * w.w;
    }
    atomicAdd(&g_logits[col + 0], acc.x);
    atomicAdd(&g_logits[col + 1], acc.y);
    atomicAdd(&g_logits[col + 2], acc.z);
    atomicAdd(&g_logits[col + 3], acc.w);
}

// -------- 4) value head: 4096 -> 64 -> 32 -> 16 -> 1 (single block) --------
__global__ void value_kernel(const float* __restrict__ wv1, const float* __restrict__ bv1,
                             const float* __restrict__ wv2, const float* __restrict__ bv2,
                             const float* __restrict__ wv3, const float* __restrict__ bv3,
                             const float* __restrict__ wv4, const float* __restrict__ bv4,
                             float* __restrict__ out) {
    __shared__ float red[256];
    __shared__ float v1[64], v2[32], v3[16];
    int t = threadIdx.x;            // 256 threads
    int o = t & 63, chunk = t >> 6; // 64 outputs x 4 row-chunks

    float acc = 0.0f;
    int i0 = chunk * (FLATD / 4);
#pragma unroll 4
    for (int i = 0; i < FLATD / 4; i++)
        acc += g_agg[i0 + i] * wv1[(size_t)(i0 + i) * 64 + o];
    red[t] = acc;
    __syncthreads();

    if (t < 64)
        v1[t] = fmaxf(red[t] + red[t + 64] + red[t + 128] + red[t + 192] + bv1[t], 0.0f);
    __syncthreads();
    if (t < 32) {
        float a = bv2[t];
#pragma unroll
        for (int k = 0; k < 64; k++) a += v1[k] * wv2[k * 32 + t];
        v2[t] = fmaxf(a, 0.0f);
    }
    __syncthreads();
    if (t < 16) {
        float a = bv3[t];
#pragma unroll
        for (int k = 0; k < 32; k++) a += v2[k] * wv3[k * 16 + t];
        v3[t] = fmaxf(a, 0.0f);
    }
    __syncthreads();
    if (t == 0) {
        float a = bv4[0];
#pragma unroll
        for (int k = 0; k < 16; k++) a += v3[k] * wv4[k];
        out[N_EDGES] = a;   // value scalar after policy[E]
    }
}

// -------- 5) softmax over 32768 logits (single 1024-thread block) --------
__global__ __launch_bounds__(1024) void softmax_kernel(float* __restrict__ out) {
    __shared__ float red[32];
    int t = threadIdx.x;
    float v[32];
    float mx = -CUDART_INF_F;
#pragma unroll
    for (int p = 0; p < 32; p++) {
        v[p] = g_logits[p * 1024 + t];
        mx = fmaxf(mx, v[p]);
    }
#pragma unroll
    for (int o = 16; o; o >>= 1) mx = fmaxf(mx, __shfl_xor_sync(0xFFFFFFFFu, mx, o));
    if ((t & 31) == 0) red[t >> 5] = mx;
    __syncthreads();
    if (t < 32) {
        float m = red[t];
#pragma unroll
        for (int o = 16; o; o >>= 1) m = fmaxf(m, __shfl_xor_sync(0xFFFFFFFFu, m, o));
        red[t] = m;
    }
    __syncthreads();
    mx = red[0];
    __syncthreads();

    float sum = 0.0f;
#pragma unroll
    for (int p = 0; p < 32; p++) { v[p] = expf(v[p] - mx); sum += v[p]; }
#pragma unroll
    for (int o = 16; o; o >>= 1) sum += __shfl_xor_sync(0xFFFFFFFFu, sum, o);
    if ((t & 31) == 0) red[t >> 5] = sum;
    __syncthreads();
    if (t < 32) {
        float s = red[t];
#pragma unroll
        for (int o = 16; o; o >>= 1) s += __shfl_xor_sync(0xFFFFFFFFu, s, o);
        red[t] = s;
    }
    __syncthreads();
    float inv = 1.0f / red[0];
#pragma unroll
    for (int p = 0; p < 32; p++) out[p * 1024 + t] = v[p] * inv;
}

extern "C" void kernel_launch(void* const* d_in, const int* in_sizes, int n_in,
                              void* d_out, int out_size) {
    const int*   tgt  = (const int*)  d_in[0];
    const int*   eidx = (const int*)  d_in[1];
    const float* w1   = (const float*)d_in[2];
    const float* b1   = (const float*)d_in[3];
    const float* w2   = (const float*)d_in[4];
    const float* b2   = (const float*)d_in[5];
    const float* wv1  = (const float*)d_in[6];
    const float* bv1  = (const float*)d_in[7];
    const float* wv2  = (const float*)d_in[8];
    const float* bv2  = (const float*)d_in[9];
    const float* wv3  = (const float*)d_in[10];
    const float* bv3  = (const float*)d_in[11];
    const float* wv4  = (const float*)d_in[12];
    const float* bv4  = (const float*)d_in[13];
    const float* wp   = (const float*)d_in[14];
    const float* bp   = (const float*)d_in[15];
    float* out = (float*)d_out;

    init_kernel<<<(N_EDGES + 255) / 256, 256>>>(bp);
    edge_kernel<<<(N_EDGES + 255) / 256, 256>>>(tgt, eidx, w1, b1, w2, b2);
    dim3 g(N_EDGES / COLS_PER_BLK, FLATD / ROWS_PER_BLK);  // (32, 16)
    gemv_kernel<<<g, 256>>>(wp);
    value_kernel<<<1, 256>>>(wv1, bv1, wv2, bv2, wv3, bv3, wv4, bv4, out);
    softmax_kernel<<<1, 1024>>>(out);
}

// round 2
// speedup vs baseline: 1.3954x; 1.3954x over previous
#include <cuda_runtime.h>
#include <math_constants.h>

#define N_NODES 1024
#define N_EDGES 32768
#define FLATD   4096   // 4*N

// -------- scratch (no allocation allowed; device globals) --------
__device__ float g_agg[FLATD];       // aggregated EdgeConv output, layout [n*4 + c]
__device__ float g_logits[N_EDGES];  // policy logits
__device__ float g_v1[64];           // value-head layer-1 pre-activation

// -------- 1) init: zero agg, seed logits with bp, seed v1 with bv1 --------
__global__ void init_kernel(const float* __restrict__ bp,
                            const float* __restrict__ bv1) {
    int j = blockIdx.x * blockDim.x + threadIdx.x;
    if (j < N_EDGES) g_logits[j] = bp[j];
    if (j < FLATD)   g_agg[j] = 0.0f;
    if (j < 64)      g_v1[j] = bv1[j];
}

// -------- 2) EdgeConv collapsed through the one-hot --------
__global__ void edge_kernel(const int* __restrict__ tgt,
                            const int* __restrict__ eidx,
                            const float* __restrict__ w1,
                            const float* __restrict__ b1,
                            const float* __restrict__ w2,
                            const float* __restrict__ b2) {
    int e = blockIdx.x * blockDim.x + threadIdx.x;
    if (e >= N_EDGES) return;
    int s = eidx[e];            // edge_index[0][e]  (source)
    int d = eidx[N_EDGES + e];  // edge_index[1][e]  (dest / aggregation node)
    int ti = tgt[d];
    int tj = tgt[s];

    float h[10];
#pragma unroll
    for (int k = 0; k < 10; k++) h[k] = b1[k];
    if (ti >= 0) {
#pragma unroll
        for (int k = 0; k < 10; k++)
            h[k] += w1[ti * 10 + k] - w1[(N_NODES + ti) * 10 + k];
    }
    if (tj >= 0) {
#pragma unroll
        for (int k = 0; k < 10; k++)
            h[k] += w1[(N_NODES + tj) * 10 + k];
    }
#pragma unroll
    for (int k = 0; k < 10; k++) h[k] = fmaxf(h[k], 0.0f);

    float m[4];
#pragma unroll
    for (int c = 0; c < 4; c++) {
        float acc = b2[c];
#pragma unroll
        for (int k = 0; k < 10; k++) acc += h[k] * w2[k * 4 + c];
        m[c] = acc;
    }
    float mx = fmaxf(fmaxf(m[0], m[1]), fmaxf(m[2], m[3]));
    float sum = 0.0f;
#pragma unroll
    for (int c = 0; c < 4; c++) { m[c] = expf(m[c] - mx); sum += m[c]; }
    float inv = 1.0f / sum;
#pragma unroll
    for (int c = 0; c < 4; c++)
        atomicAdd(&g_agg[d * 4 + c], m[c] * inv);
}

// -------- 3a) value head layer 1: 4096 -> 64, split over 16 blocks --------
__global__ __launch_bounds__(256) void value1_kernel(const float* __restrict__ wv1) {
    __shared__ float red[256];
    int t = threadIdx.x;            // 256 threads
    int o = t & 63, chunk = t >> 6; // 64 outputs x 4 row-sub-chunks
    int row0 = blockIdx.x * 256 + chunk * 64;

    float acc = 0.0f;
#pragma unroll 8
    for (int i = 0; i < 64; i++)
        acc += g_agg[row0 + i] * wv1[(size_t)(row0 + i) * 64 + o];
    red[t] = acc;
    __syncthreads();
    if (t < 64)
        atomicAdd(&g_v1[t], red[t] + red[t + 64] + red[t + 128] + red[t + 192]);
}

// -------- 3b) value tail: relu(v1) -> 32 -> 16 -> 1 (one tiny block) --------
__global__ void value2_kernel(const float* __restrict__ wv2, const float* __restrict__ bv2,
                              const float* __restrict__ wv3, const float* __restrict__ bv3,
                              const float* __restrict__ wv4, const float* __restrict__ bv4,
                              float* __restrict__ out) {
    __shared__ float v1[64], v2[32], v3[16];
    int t = threadIdx.x;  // 64 threads
    v1[t] = fmaxf(g_v1[t], 0.0f);
    __syncthreads();
    if (t < 32) {
        float a = bv2[t];
#pragma unroll
        for (int k = 0; k < 64; k++) a += v1[k] * wv2[k * 32 + t];
        v2[t] = fmaxf(a, 0.0f);
    }
    __syncthreads();
    if (t < 16) {
        float a = bv3[t];
#pragma unroll
        for (int k = 0; k < 32; k++) a += v2[k] * wv3[k * 16 + t];
        v3[t] = fmaxf(a, 0.0f);
    }
    __syncthreads();
    if (t == 0) {
        float a = bv4[0];
#pragma unroll
        for (int k = 0; k < 16; k++) a += v3[k] * wv4[k];
        out[N_EDGES] = a;   // value scalar after policy[E]
    }
}

// -------- 4) policy GEMV: logits += flat @ wp  (512 MB stream, HBM-bound) --------
#define ROWS_PER_BLK 256   // FLATD / 16 row-slices
#define COLS_PER_BLK 1024  // 256 threads * 4 cols (float4)

__global__ __launch_bounds__(256) void gemv_kernel(const float* __restrict__ wp) {
    __shared__ float sx[ROWS_PER_BLK];
    int t    = threadIdx.x;
    int col  = blockIdx.x * COLS_PER_BLK + t * 4;
    int row0 = blockIdx.y * ROWS_PER_BLK;

    sx[t] = g_agg[row0 + t];   // blockDim == ROWS_PER_BLK == 256
    __syncthreads();

    float4 acc = make_float4(0.f, 0.f, 0.f, 0.f);
    const float4* wptr = reinterpret_cast<const float4*>(
        wp + (size_t)row0 * N_EDGES + col);
    const size_t stride4 = N_EDGES / 4;

#pragma unroll 4
    for (int i = 0; i < ROWS_PER_BLK; i++) {
        float  xv = sx[i];
        float4 w  = __ldcs(wptr + (size_t)i * stride4);  // streaming: no reuse
        acc.x += xv * w.x;
        acc.y += xv * w.y;
        acc.z += xv * w.z;
        acc.w += xv * w.w;
    }
    atomicAdd(&g_logits[col + 0], acc.x);
    atomicAdd(&g_logits[col + 1], acc.y);
    atomicAdd(&g_logits[col + 2], acc.z);
    atomicAdd(&g_logits[col + 3], acc.w);
}

// -------- 5) softmax over 32768 logits (single 1024-thread block) --------
__global__ __launch_bounds__(1024) void softmax_kernel(float* __restrict__ out) {
    __shared__ float red[32];
    int t = threadIdx.x;
    float v[32];
    float mx = -CUDART_INF_F;
#pragma unroll
    for (int p = 0; p < 32; p++) {
        v[p] = g_logits[p * 1024 + t];
        mx = fmaxf(mx, v[p]);
    }
#pragma unroll
    for (int o = 16; o; o >>= 1) mx = fmaxf(mx, __shfl_xor_sync(0xFFFFFFFFu, mx, o));
    if ((t & 31) == 0) red[t >> 5] = mx;
    __syncthreads();
    if (t < 32) {
        float m = red[t];
#pragma unroll
        for (int o = 16; o; o >>= 1) m = fmaxf(m, __shfl_xor_sync(0xFFFFFFFFu, m, o));
        red[t] = m;
    }
    __syncthreads();
    mx = red[0];
    __syncthreads();

    float sum = 0.0f;
#pragma unroll
    for (int p = 0; p < 32; p++) { v[p] = expf(v[p] - mx); sum += v[p]; }
#pragma unroll
    for (int o = 16; o; o >>= 1) sum += __shfl_xor_sync(0xFFFFFFFFu, sum, o);
    if ((t & 31) == 0) red[t >> 5] = sum;
    __syncthreads();
    if (t < 32) {
        float s = red[t];
#pragma unroll
        for (int o = 16; o; o >>= 1) s += __shfl_xor_sync(0xFFFFFFFFu, s, o);
        red[t] = s;
    }
    __syncthreads();
    float inv = 1.0f / red[0];
#pragma unroll
    for (int p = 0; p < 32; p++) out[p * 1024 + t] = v[p] * inv;
}

extern "C" void kernel_launch(void* const* d_in, const int* in_sizes, int n_in,
                              void* d_out, int out_size) {
    const int*   tgt  = (const int*)  d_in[0];
    const int*   eidx = (const int*)  d_in[1];
    const float* w1   = (const float*)d_in[2];
    const float* b1   = (const float*)d_in[3];
    const float* w2   = (const float*)d_in[4];
    const float* b2   = (const float*)d_in[5];
    const float* wv1  = (const float*)d_in[6];
    const float* bv1  = (const float*)d_in[7];
    const float* wv2  = (const float*)d_in[8];
    const float* bv2  = (const float*)d_in[9];
    const float* wv3  = (const float*)d_in[10];
    const float* bv3  = (const float*)d_in[11];
    const float* wv4  = (const float*)d_in[12];
    const float* bv4  = (const float*)d_in[13];
    const float* wp   = (const float*)d_in[14];
    const float* bp   = (const float*)d_in[15];
    float* out = (float*)d_out;

    init_kernel<<<(N_EDGES + 255) / 256, 256>>>(bp, bv1);
    edge_kernel<<<(N_EDGES + 255) / 256, 256>>>(tgt, eidx, w1, b1, w2, b2);
    value1_kernel<<<16, 256>>>(wv1);
    value2_kernel<<<1, 64>>>(wv2, bv2, wv3, bv3, wv4, bv4, out);
    dim3 g(N_EDGES / COLS_PER_BLK, FLATD / ROWS_PER_BLK);  // (32, 16)
    gemv_kernel<<<g, 256>>>(wp);
    softmax_kernel<<<1, 1024>>>(out);
}

// round 3
// speedup vs baseline: 1.4937x; 1.0704x over previous
#include <cuda_runtime.h>
#include <math_constants.h>

#define N_NODES 1024
#define N_EDGES 32768
#define FLATD   4096   // 4*N

// -------- scratch (device globals; zero-initialized at module load) --------
// Invariant maintained by every call: on entry g_agg == 0, g_logits == 0,
// g_v1 == bv1-seed-pending (g_v1 == 0 first call -> handled: value1 adds raw
// partials, tail adds bv1 explicitly; we keep g_v1 zeroed between calls).
__device__ float g_agg[FLATD];       // aggregated EdgeConv output [n*4 + c]
__device__ float g_logits[N_EDGES];  // policy logits (accumulated, no bias)
__device__ float g_v1[64];           // value-head layer-1 partial sums (no bias)

// -------- 1) EdgeConv collapsed through the one-hot --------
__global__ void edge_kernel(const int* __restrict__ tgt,
                            const int* __restrict__ eidx,
                            const float* __restrict__ w1,
                            const float* __restrict__ b1,
                            const float* __restrict__ w2,
                            const float* __restrict__ b2) {
    int e = blockIdx.x * blockDim.x + threadIdx.x;
    if (e >= N_EDGES) return;
    int s = eidx[e];            // edge_index[0][e]  (source)
    int d = eidx[N_EDGES + e];  // edge_index[1][e]  (dest / aggregation node)
    int ti = tgt[d];
    int tj = tgt[s];

    float h[10];
#pragma unroll
    for (int k = 0; k < 10; k++) h[k] = b1[k];
    if (ti >= 0) {
#pragma unroll
        for (int k = 0; k < 10; k++)
            h[k] += w1[ti * 10 + k] - w1[(N_NODES + ti) * 10 + k];
    }
    if (tj >= 0) {
#pragma unroll
        for (int k = 0; k < 10; k++)
            h[k] += w1[(N_NODES + tj) * 10 + k];
    }
#pragma unroll
    for (int k = 0; k < 10; k++) h[k] = fmaxf(h[k], 0.0f);

    float m[4];
#pragma unroll
    for (int c = 0; c < 4; c++) {
        float acc = b2[c];
#pragma unroll
        for (int k = 0; k < 10; k++) acc += h[k] * w2[k * 4 + c];
        m[c] = acc;
    }
    float mx = fmaxf(fmaxf(m[0], m[1]), fmaxf(m[2], m[3]));
    float sum = 0.0f;
#pragma unroll
    for (int c = 0; c < 4; c++) { m[c] = expf(m[c] - mx); sum += m[c]; }
    float inv = 1.0f / sum;
#pragma unroll
    for (int c = 0; c < 4; c++)
        atomicAdd(&g_agg[d * 4 + c], m[c] * inv);
}

// -------- 2) fused: policy GEMV (blocks 0..1023) + value layer1 (blocks 1024..1039) --------
#define ROWS_PER_BLK 128   // FLATD / 32 row-slices
#define COLS_PER_BLK 1024  // 256 threads * 4 cols (float4)
#define GEMV_BLOCKS  1024  // 32 col-blocks * 32 row-slices
#define V1_BLOCKS    16

__global__ __launch_bounds__(256) void gemv_fused_kernel(const float* __restrict__ wp,
                                                         const float* __restrict__ wv1) {
    int b = blockIdx.x;
    int t = threadIdx.x;

    if (b < GEMV_BLOCKS) {
        __shared__ float sx[ROWS_PER_BLK];
        int bx = b & 31;           // col block
        int by = b >> 5;           // row slice
        int col  = bx * COLS_PER_BLK + t * 4;
        int row0 = by * ROWS_PER_BLK;

        if (t < ROWS_PER_BLK) sx[t] = g_agg[row0 + t];
        __syncthreads();

        float4 acc = make_float4(0.f, 0.f, 0.f, 0.f);
        const float4* wptr = reinterpret_cast<const float4*>(
            wp + (size_t)row0 * N_EDGES + col);
        const size_t stride4 = N_EDGES / 4;

#pragma unroll 8
        for (int i = 0; i < ROWS_PER_BLK; i++) {
            float  xv = sx[i];
            float4 w  = __ldcs(wptr + (size_t)i * stride4);  // streaming, no reuse
            acc.x += xv * w.x;
            acc.y += xv * w.y;
            acc.z += xv * w.z;
            acc.w += xv * w.w;
        }
        atomicAdd(&g_logits[col + 0], acc.x);
        atomicAdd(&g_logits[col + 1], acc.y);
        atomicAdd(&g_logits[col + 2], acc.z);
        atomicAdd(&g_logits[col + 3], acc.w);
    } else {
        // value head layer 1: 4096 -> 64, 16 blocks x 256 rows each
        __shared__ float red[256];
        int vb = b - GEMV_BLOCKS;
        int o = t & 63, chunk = t >> 6;        // 64 outputs x 4 row-sub-chunks
        int row0 = vb * 256 + chunk * 64;

        float acc = 0.0f;
#pragma unroll 8
        for (int i = 0; i < 64; i++)
            acc += g_agg[row0 + i] * wv1[(size_t)(row0 + i) * 64 + o];
        red[t] = acc;
        __syncthreads();
        if (t < 64)
            atomicAdd(&g_v1[t], red[t] + red[t + 64] + red[t + 128] + red[t + 192]);
    }
}

// -------- 3) fused: softmax (block 0) + value tail & state reset (block 1) --------
__global__ __launch_bounds__(1024) void softmax_fused_kernel(
        const float* __restrict__ bp,
        const float* __restrict__ bv1,
        const float* __restrict__ wv2, const float* __restrict__ bv2,
        const float* __restrict__ wv3, const float* __restrict__ bv3,
        const float* __restrict__ wv4, const float* __restrict__ bv4,
        float* __restrict__ out) {
    int t = threadIdx.x;

    if (blockIdx.x == 0) {
        // ---- softmax over 32768 logits, 1024 threads, 32 values each ----
        __shared__ float red[32];
        float v[32];
        float mx = -CUDART_INF_F;
#pragma unroll
        for (int p = 0; p < 32; p++) {
            int idx = p * 1024 + t;
            v[p] = g_logits[idx] + bp[idx];
            g_logits[idx] = 0.0f;          // restore zero-state for next call
            mx = fmaxf(mx, v[p]);
        }
#pragma unroll
        for (int o = 16; o; o >>= 1) mx = fmaxf(mx, __shfl_xor_sync(0xFFFFFFFFu, mx, o));
        if ((t & 31) == 0) red[t >> 5] = mx;
        __syncthreads();
        if (t < 32) {
            float m = red[t];
#pragma unroll
            for (int o = 16; o; o >>= 1) m = fmaxf(m, __shfl_xor_sync(0xFFFFFFFFu, m, o));
            red[t] = m;
        }
        __syncthreads();
        mx = red[0];
        __syncthreads();

        float sum = 0.0f;
#pragma unroll
        for (int p = 0; p < 32; p++) { v[p] = expf(v[p] - mx); sum += v[p]; }
#pragma unroll
        for (int o = 16; o; o >>= 1) sum += __shfl_xor_sync(0xFFFFFFFFu, sum, o);
        if ((t & 31) == 0) red[t >> 5] = sum;
        __syncthreads();
        if (t < 32) {
            float s = red[t];
#pragma unroll
            for (int o = 16; o; o >>= 1) s += __shfl_xor_sync(0xFFFFFFFFu, s, o);
            red[t] = s;
        }
        __syncthreads();
        float inv = 1.0f / red[0];
#pragma unroll
        for (int p = 0; p < 32; p++) out[p * 1024 + t] = v[p] * inv;
    } else {
        // ---- value tail: relu(v1+bv1) -> 32 -> 16 -> 1, then reset state ----
        __shared__ float v1[64], v2[32], v3[16];
        if (t < 64) {
            v1[t] = fmaxf(g_v1[t] + bv1[t], 0.0f);
            g_v1[t] = 0.0f;                // restore zero-state
        }
        __syncthreads();
        if (t < 32) {
            float a = bv2[t];
#pragma unroll
            for (int k = 0; k < 64; k++) a += v1[k] * wv2[k * 32 + t];
            v2[t] = fmaxf(a, 0.0f);
        }
        // reset g_agg for next call (4096 floats / 256 threads = 16 each)
#pragma unroll
        for (int i = 0; i < FLATD / 256; i++)
            g_agg[i * 256 + t] = 0.0f;
        __syncthreads();
        if (t < 16) {
            float a = bv3[t];
#pragma unroll
            for (int k = 0; k < 32; k++) a += v2[k] * wv3[k * 16 + t];
            v3[t] = fmaxf(a, 0.0f);
        }
        __syncthreads();
        if (t == 0) {
            float a = bv4[0];
#pragma unroll
            for (int k = 0; k < 16; k++) a += v3[k] * wv4[k];
            out[N_EDGES] = a;   // value scalar after policy[E]
        }
    }
}

extern "C" void kernel_launch(void* const* d_in, const int* in_sizes, int n_in,
                              void* d_out, int out_size) {
    const int*   tgt  = (const int*)  d_in[0];
    const int*   eidx = (const int*)  d_in[1];
    const float* w1   = (const float*)d_in[2];
    const float* b1   = (const float*)d_in[3];
    const float* w2   = (const float*)d_in[4];
    const float* b2   = (const float*)d_in[5];
    const float* wv1  = (const float*)d_in[6];
    const float* bv1  = (const float*)d_in[7];
    const float* wv2  = (const float*)d_in[8];
    const float* bv2  = (const float*)d_in[9];
    const float* wv3  = (const float*)d_in[10];
    const float* bv3  = (const float*)d_in[11];
    const float* wv4  = (const float*)d_in[12];
    const float* bv4  = (const float*)d_in[13];
    const float* wp   = (const float*)d_in[14];
    const float* bp   = (const float*)d_in[15];
    float* out = (float*)d_out;

    edge_kernel<<<(N_EDGES + 255) / 256, 256>>>(tgt, eidx, w1, b1, w2, b2);
    gemv_fused_kernel<<<GEMV_BLOCKS + V1_BLOCKS, 256>>>(wp, wv1);
    softmax_fused_kernel<<<2, 1024>>>(bp, bv1, wv2, bv2, wv3, bv3, wv4, bv4, out);
}